// round 16
// baseline (speedup 1.0000x reference)
#include <cuda_runtime.h>

// x: (B=256, F=2048, J=25, C=2) fp32 row-major. Row = 50 floats = 200 B.
// theta = w[0] only (reference's loop returns early). Joints 0..7 rotated:
//   nx = c*x + s*y ; ny = c*y - s*x   (out = x @ [[c,-s],[s,c]])
// Joints 8..24 passthrough.
//
// Persistent single-wave grid-stride kernel:
//   n8 = 3,276,800 v8-chunks = 2^17 * 25.
//   512 CTAs x 256 threads = 131,072 threads (fits in ONE wave on 148 SMs),
//   each thread processes exactly 25 chunks at stride 131,072 (coalesced,
//   no predicates). Joint index advances by (131072*4) % 25 == 13 per iter.
//   #pragma unroll 5 -> 5 independent front-batched LDG.256 per group.
// Setup (sincos + mod) runs once per thread for the whole kernel; zero
// wave transitions, zero CTA dispatch churn during the run.

struct f8 { float v[8]; };

__device__ __forceinline__ f8 ldg256(const float* p) {
    f8 r;
    asm volatile("ld.global.nc.v8.f32 {%0,%1,%2,%3,%4,%5,%6,%7}, [%8];"
                 : "=f"(r.v[0]), "=f"(r.v[1]), "=f"(r.v[2]), "=f"(r.v[3]),
                   "=f"(r.v[4]), "=f"(r.v[5]), "=f"(r.v[6]), "=f"(r.v[7])
                 : "l"(p));
    return r;
}

__device__ __forceinline__ void stg256(float* p, const f8& r) {
    asm volatile("st.global.v8.f32 [%0], {%1,%2,%3,%4,%5,%6,%7,%8};"
                 :: "l"(p),
                    "f"(r.v[0]), "f"(r.v[1]), "f"(r.v[2]), "f"(r.v[3]),
                    "f"(r.v[4]), "f"(r.v[5]), "f"(r.v[6]), "f"(r.v[7])
                 : "memory");
}

__device__ __forceinline__ void rot2(float& px, float& py, float c, float s) {
    float nx = fmaf(c, px, s * py);
    float ny = fmaf(c, py, -s * px);
    px = nx; py = ny;
}

__device__ __forceinline__ unsigned wrap25(unsigned j) {
    return (j >= 25u) ? j - 25u : j;
}

// Rotate the joint<8 pairs inside one 8-float chunk whose first pair has
// joint index j0 (consecutive pairs, joint wraps at 25).
__device__ __forceinline__ void rot_chunk(f8& a, unsigned j0, float c, float s) {
    unsigned j = j0;
#pragma unroll
    for (int t = 0; t < 4; t++) {
        if (j < 8u) rot2(a.v[2 * t], a.v[2 * t + 1], c, s);
        j = wrap25(j + 1u);
    }
}

static constexpr int NTHREADS_TOTAL = 512 * 256;   // 131,072 = 2^17

// Persistent bulk kernel: each thread handles `iters` chunks at stride
// NTHREADS_TOTAL. Grid covers exactly iters*NTHREADS_TOTAL chunks.
__global__ void __launch_bounds__(256)
rt_rotate(const float* __restrict__ x, float* __restrict__ out,
          const float* __restrict__ w, int iters) {
    const int tid = blockIdx.x * 256 + threadIdx.x;  // 0..131071

    float s, c;
    __sincosf(__ldg(w), &s, &c);

    const float* px = x + (size_t)tid * 8;
    float*       po = out + (size_t)tid * 8;
    unsigned j = ((unsigned)tid * 4u) % 25u;         // joint of pair 0
    // per-iter: +131072 chunks = +524288 pairs; 524288 % 25 == 13

#pragma unroll 5
    for (int k = 0; k < iters; k++) {
        f8 a = ldg256(px);
        rot_chunk(a, j, c, s);
        stg256(po, a);
        px += (size_t)NTHREADS_TOTAL * 8;
        po += (size_t)NTHREADS_TOTAL * 8;
        j = wrap25(j + 13u);
    }
}

// Scalar tail: handles pairs [pair_lo, pair_hi). Unused at this shape.
__global__ void rt_tail(const float* __restrict__ x, float* __restrict__ out,
                        const float* __restrict__ w, int pair_lo, int pair_hi) {
    int p = pair_lo + blockIdx.x * blockDim.x + threadIdx.x;
    if (p >= pair_hi) return;
    float s, c;
    __sincosf(__ldg(w), &s, &c);
    float px = x[2 * p], py = x[2 * p + 1];
    unsigned j = (unsigned)p % 25u;
    if (j < 8u) rot2(px, py, c, s);
    out[2 * p] = px;
    out[2 * p + 1] = py;
}

extern "C" void kernel_launch(void* const* d_in, const int* in_sizes, int n_in,
                              void* d_out, int out_size) {
    const float* x = (const float*)d_in[0];
    const float* w = (const float*)d_in[1];
    float* out = (float*)d_out;

    int n = in_sizes[0];              // 26,214,400 floats
    int n8 = n / 8;                   // 3,276,800 v8 chunks (8 | n here)
    int iters = n8 / NTHREADS_TOTAL;  // 25 at this shape

    if (iters > 0)
        rt_rotate<<<512, 256>>>(x, out, w, iters);

    // Remainder coverage (floats beyond iters*NTHREADS_TOTAL*8). Zero here.
    int done_pairs = iters * NTHREADS_TOTAL * 4;
    int total_pairs = n / 2;
    if (total_pairs > done_pairs) {
        int rem = total_pairs - done_pairs;
        rt_tail<<<(rem + 255) / 256, 256>>>(x, out, w, done_pairs, total_pairs);
    }
}

// round 17
// speedup vs baseline: 1.1215x; 1.1215x over previous
#include <cuda_runtime.h>

// x: (B=256, F=2048, J=25, C=2) fp32 row-major. Row = 50 floats = 200 B.
// theta = w[0] only (reference's loop returns early). Joints 0..7 rotated:
//   nx = c*x + s*y ; ny = c*y - s*x   (out = x @ [[c,-s],[s,c]])
// Joints 8..24 passthrough.
//
// FINAL configuration (best measured across R2-R16 experiment matrix):
//   - 256-bit global ld/st (sm_100+ ld/st.global.v8.f32)
//   - 2 chunks per thread at +256 (blockDim) stride, 256-thread CTAs,
//     6400 blocks (many small CTAs -> max warp residency feeds DRAM)
//   - fused uniform __sincosf (2 MUFU/warp, hidden under DRAM stream)
//   - no bounds predicates in bulk kernel (grid divides data exactly);
//     scalar tail kernel covers any remainder (zero at this shape)
// Measured regressions (reverted): MLP=4, L2 evict hints, 512-thread CTAs,
// persistent single-wave grid-stride.

struct f8 { float v[8]; };

__device__ __forceinline__ f8 ldg256(const float* p) {
    f8 r;
    asm volatile("ld.global.nc.v8.f32 {%0,%1,%2,%3,%4,%5,%6,%7}, [%8];"
                 : "=f"(r.v[0]), "=f"(r.v[1]), "=f"(r.v[2]), "=f"(r.v[3]),
                   "=f"(r.v[4]), "=f"(r.v[5]), "=f"(r.v[6]), "=f"(r.v[7])
                 : "l"(p));
    return r;
}

__device__ __forceinline__ void stg256(float* p, const f8& r) {
    asm volatile("st.global.v8.f32 [%0], {%1,%2,%3,%4,%5,%6,%7,%8};"
                 :: "l"(p),
                    "f"(r.v[0]), "f"(r.v[1]), "f"(r.v[2]), "f"(r.v[3]),
                    "f"(r.v[4]), "f"(r.v[5]), "f"(r.v[6]), "f"(r.v[7])
                 : "memory");
}

__device__ __forceinline__ void rot2(float& px, float& py, float c, float s) {
    float nx = fmaf(c, px, s * py);
    float ny = fmaf(c, py, -s * px);
    px = nx; py = ny;
}

__device__ __forceinline__ unsigned wrap25(unsigned j) {
    return (j >= 25u) ? j - 25u : j;
}

// Rotate the joint<8 pairs inside one 8-float chunk whose first pair has
// joint index j0 (consecutive pairs, joint wraps at 25).
__device__ __forceinline__ void rot_chunk(f8& a, unsigned j0, float c, float s) {
    unsigned j = j0;
#pragma unroll
    for (int t = 0; t < 4; t++) {
        if (j < 8u) rot2(a.v[2 * t], a.v[2 * t + 1], c, s);
        j = wrap25(j + 1u);
    }
}

// Bulk kernel: grid covers exactly gridDim.x*512 chunks, no predicates.
__global__ void __launch_bounds__(256)
rt_rotate(const float* __restrict__ x, float* __restrict__ out,
          const float* __restrict__ w) {
    const int c0 = blockIdx.x * 512 + threadIdx.x;   // first v8 chunk
    const int c1 = c0 + 256;                         // second v8 chunk

    float s, c;
    __sincosf(__ldg(w), &s, &c);

    f8 a0 = ldg256(x + (size_t)c0 * 8);
    f8 a1 = ldg256(x + (size_t)c1 * 8);

    unsigned j0 = ((unsigned)c0 * 4u) % 25u;         // joint of chunk0 pair0
    unsigned j1 = (j0 == 0u) ? 24u : j0 - 1u;        // +1024 pairs ≡ -1 mod 25

    rot_chunk(a0, j0, c, s);
    rot_chunk(a1, j1, c, s);

    stg256(out + (size_t)c0 * 8, a0);
    stg256(out + (size_t)c1 * 8, a1);
}

// Scalar tail: handles pairs [pair_lo, pair_hi). Unused at this shape.
__global__ void rt_tail(const float* __restrict__ x, float* __restrict__ out,
                        const float* __restrict__ w, int pair_lo, int pair_hi) {
    int p = pair_lo + blockIdx.x * blockDim.x + threadIdx.x;
    if (p >= pair_hi) return;
    float s, c;
    __sincosf(__ldg(w), &s, &c);
    float px = x[2 * p], py = x[2 * p + 1];
    unsigned j = (unsigned)p % 25u;
    if (j < 8u) rot2(px, py, c, s);
    out[2 * p] = px;
    out[2 * p + 1] = py;
}

extern "C" void kernel_launch(void* const* d_in, const int* in_sizes, int n_in,
                              void* d_out, int out_size) {
    const float* x = (const float*)d_in[0];
    const float* w = (const float*)d_in[1];
    float* out = (float*)d_out;

    int n = in_sizes[0];            // 26,214,400 floats
    int n8 = n / 8;                 // 3,276,800 v8 chunks (8 | n here)
    int blocks = n8 / 512;          // 6400 full blocks, exact at this shape

    if (blocks > 0)
        rt_rotate<<<blocks, 256>>>(x, out, w);

    // Remainder coverage (floats beyond blocks*512*8). Zero at this shape.
    int done_pairs = blocks * 512 * 4;
    int total_pairs = n / 2;
    if (total_pairs > done_pairs) {
        int rem = total_pairs - done_pairs;
        rt_tail<<<(rem + 255) / 256, 256>>>(x, out, w, done_pairs, total_pairs);
    }
}